// round 2
// baseline (speedup 1.0000x reference)
#include <cuda_runtime.h>
#include <cuda_bf16.h>
#include <math.h>

// ---------------- constants ----------------
#define BB 16
#define CC 256
#define HH 64
#define WW 64
#define NN 4096            // tokens per batch
#define BN (BB*NN)         // 65536 total tokens
#define CRD 128
#define NHD 8
#define NRD 16             // reduced tokens (4x4)
#define HID 1024
#define HALF 512

// ---------------- scratch (device globals; no allocation) ----------------
__device__ float g_xh[BB*CC*HH];          // row gates
__device__ float g_xw[BB*CC*WW];          // col gates
__device__ float g_res[(size_t)BN*CC];    // gated tokens -> later t2
__device__ float g_tln[(size_t)BN*CC];    // LN1 out -> later LN2 out
__device__ float g_q[(size_t)BN*CRD];
__device__ float g_o[(size_t)BN*CC];      // attention output tokens
__device__ float g_red[BB*CC*NRD];        // reduced+dw map tokens
__device__ float g_k[BB*NRD*CRD];
__device__ float g_v[BB*NRD*CC];
__device__ float g_h[(size_t)BN*HID];     // fc1 output (gelu'd)
__device__ float g_x2i[(size_t)BB*HALF*NN]; // gnormed x2, image layout
__device__ float g_x2c[(size_t)BB*HALF*NN]; // after gconv, image layout
__device__ float g_gate[(size_t)BN*HALF];   // x1*x2 token layout

__device__ __forceinline__ float gelu_f(float v){
    return 0.5f * v * (1.0f + erff(v * 0.70710678118654752f));
}

// ---------------- K1: row/col means of x ----------------
__global__ void k_mean(const float* __restrict__ x){
    int bc = blockIdx.x;                      // b*256+c
    __shared__ float s[64][65];
    const float* p = x + (size_t)bc*4096;
    for (int i = threadIdx.x; i < 4096; i += 256) s[i>>6][i&63] = p[i];
    __syncthreads();
    int t = threadIdx.x;
    if (t < 64){
        float su = 0.f;
        #pragma unroll 8
        for (int w = 0; w < 64; w++) su += s[t][w];
        g_xh[bc*64 + t] = su * (1.0f/64.0f);
    } else if (t < 128){
        int w = t - 64;
        float su = 0.f;
        #pragma unroll 8
        for (int h = 0; h < 64; h++) su += s[h][w];
        g_xw[bc*64 + w] = su * (1.0f/64.0f);
    }
}

// ---------------- K2: dwconv1d(k=7,p=3) + GroupNorm(16) + ReLU, in-place on g_xh/g_xw ----------------
__global__ void k_sdam(const float* __restrict__ w7,
                       const float* __restrict__ gnw, const float* __restrict__ gnb){
    int id = blockIdx.x;            // b*32 + g*2 + which
    int which = id & 1;
    int g = (id >> 1) & 15;
    int b = id >> 5;
    float* src = which ? g_xw : g_xh;
    __shared__ float si[16][64];
    __shared__ float so[16][64];
    __shared__ float r1[256], r2[256];
    int base = (b*256 + g*16) * 64;
    for (int i = threadIdx.x; i < 1024; i += 256) si[i>>6][i&63] = src[base + i];
    __syncthreads();
    float p1 = 0.f, p2 = 0.f;
    for (int i = threadIdx.x; i < 1024; i += 256){
        int c = i >> 6, l = i & 63;
        const float* wk = w7 + (g*16 + c)*7;
        float acc = 0.f;
        #pragma unroll
        for (int k = 0; k < 7; k++){
            int ll = l - 3 + k;
            if (ll >= 0 && ll < 64) acc += si[c][ll] * wk[k];
        }
        so[c][l] = acc;
        p1 += acc; p2 += acc*acc;
    }
    r1[threadIdx.x] = p1; r2[threadIdx.x] = p2;
    __syncthreads();
    for (int st = 128; st > 0; st >>= 1){
        if (threadIdx.x < st){ r1[threadIdx.x] += r1[threadIdx.x+st]; r2[threadIdx.x] += r2[threadIdx.x+st]; }
        __syncthreads();
    }
    float mean = r1[0] * (1.0f/1024.0f);
    float var  = r2[0] * (1.0f/1024.0f) - mean*mean;
    float iv = rsqrtf(var + 1e-5f);
    for (int i = threadIdx.x; i < 1024; i += 256){
        int c = i >> 6, l = i & 63;
        float v = (so[c][l] - mean) * iv * gnw[g*16 + c] + gnb[g*16 + c];
        src[base + i] = fmaxf(v, 0.f);
    }
}

// ---------------- K3: gate x by xh*xw and transpose to tokens (g_res) ----------------
__global__ void k_gate(const float* __restrict__ x){
    int b = blockIdx.z >> 6, h = blockIdx.z & 63;
    int c0 = blockIdx.y * 32, w0 = blockIdx.x * 32;
    __shared__ float t2[32][33];
    int tx = threadIdx.x, ty = threadIdx.y;
    for (int r = ty; r < 32; r += 8){
        int c = c0 + r;
        int w = w0 + tx;
        t2[r][tx] = x[((size_t)(b*256 + c)*64 + h)*64 + w]
                  * g_xh[(b*256 + c)*64 + h] * g_xw[(b*256 + c)*64 + w];
    }
    __syncthreads();
    for (int r = ty; r < 32; r += 8){
        int w = w0 + r;
        g_res[((size_t)(b*4096) + h*64 + w)*256 + c0 + tx] = t2[tx][r];
    }
}

// ---------------- generic token LN over 256 (warp per token) ----------------
__global__ void k_ln256(const float* __restrict__ in, float* __restrict__ out,
                        const float* __restrict__ w, const float* __restrict__ bb, float eps){
    int token = blockIdx.x*8 + (threadIdx.x >> 5);
    int lane = threadIdx.x & 31;
    const float* p = in + (size_t)token*256;
    float s = 0.f, q = 0.f;
    #pragma unroll
    for (int i = lane; i < 256; i += 32){ float v = p[i]; s += v; q += v*v; }
    #pragma unroll
    for (int off = 16; off > 0; off >>= 1){
        s += __shfl_xor_sync(0xffffffff, s, off);
        q += __shfl_xor_sync(0xffffffff, q, off);
    }
    float m = s * (1.0f/256.0f);
    float var = q * (1.0f/256.0f) - m*m;
    float iv = rsqrtf(var + eps);
    #pragma unroll
    for (int i = lane; i < 256; i += 32)
        out[(size_t)token*256 + i] = (p[i] - m) * iv * w[i] + bb[i];
}

// ---------------- K5: reduction conv chain per (b,c): 64->16->4, then dw 3x3 ----------------
__global__ void k_red(const float* __restrict__ red_w, const float* __restrict__ red_b,
                      const float* __restrict__ dw_w, const float* __restrict__ dw_b){
    int bc = blockIdx.x;
    int b = bc >> 8, c = bc & 255;
    __shared__ float rw[16];
    __shared__ float dwv[9];
    __shared__ float o1[16][16];
    __shared__ float o2[4][4];
    int t = threadIdx.x;
    if (t < 16) rw[t] = red_w[c*16 + t];
    if (t >= 16 && t < 25) dwv[t-16] = dw_w[c*9 + (t-16)];
    __syncthreads();
    float rb = red_b[c];
    {   // stage 1: 16x16
        int u = t >> 4, v = t & 15;
        float acc = 0.f;
        #pragma unroll
        for (int p = 0; p < 4; p++)
            #pragma unroll
            for (int q = 0; q < 4; q++)
                acc += g_tln[((size_t)(b*4096) + (4*u+p)*64 + (4*v+q))*256 + c] * rw[p*4+q];
        o1[u][v] = acc + rb;
    }
    __syncthreads();
    if (t < 16){ // stage 2: 4x4
        int y = t >> 2, x = t & 3;
        float acc = 0.f;
        #pragma unroll
        for (int p = 0; p < 4; p++)
            #pragma unroll
            for (int q = 0; q < 4; q++)
                acc += o1[4*y+p][4*x+q] * rw[p*4+q];
        o2[y][x] = acc + rb;
    }
    __syncthreads();
    if (t < 16){ // dw 3x3 pad1
        int y = t >> 2, x = t & 3;
        float acc = dw_b[c];
        #pragma unroll
        for (int dy = -1; dy <= 1; dy++)
            #pragma unroll
            for (int dx = -1; dx <= 1; dx++){
                int yy = y+dy, xx = x+dx;
                if (yy >= 0 && yy < 4 && xx >= 0 && xx < 4)
                    acc += o2[yy][xx] * dwv[(dy+1)*3 + dx+1];
            }
        g_red[(b*256 + c)*16 + t] = acc;
    }
}

// ---------------- K6: per batch — 1x1 conv + LN + gelu, k/v proj, CPE ----------------
__global__ void k_small(const float* __restrict__ conv_w, const float* __restrict__ conv_b,
                        const float* __restrict__ na_w, const float* __restrict__ na_b,
                        const float* __restrict__ k_w, const float* __restrict__ v_w,
                        const float* __restrict__ cpe_w, const float* __restrict__ cpe_b){
    int b = blockIdx.x;
    int tid = threadIdx.x;   // 128 threads
    __shared__ float yr[256][16];
    __shared__ float xr[16][128];
    __shared__ float vs[16][256];
    __shared__ float mu2[16], iv2[16];
    for (int i = tid; i < 4096; i += 128) yr[i>>4][i&15] = g_red[b*4096 + i];
    __syncthreads();
    // 1x1 conv: out channel = tid
    {
        float tmp[16];
        float cb = conv_b[tid];
        #pragma unroll
        for (int nr = 0; nr < 16; nr++) tmp[nr] = cb;
        for (int c = 0; c < 256; c++){
            float wv = conv_w[tid*256 + c];
            #pragma unroll
            for (int nr = 0; nr < 16; nr++) tmp[nr] += yr[c][nr] * wv;
        }
        #pragma unroll
        for (int nr = 0; nr < 16; nr++) xr[nr][tid] = tmp[nr];
    }
    __syncthreads();
    if (tid < 16){
        float s = 0.f, q = 0.f;
        for (int o = 0; o < 128; o++){ float v = xr[tid][o]; s += v; q += v*v; }
        float m = s * (1.0f/128.0f);
        float var = q * (1.0f/128.0f) - m*m;
        mu2[tid] = m; iv2[tid] = rsqrtf(var + 1e-5f);
    }
    __syncthreads();
    #pragma unroll
    for (int nr = 0; nr < 16; nr++){
        float v = (xr[nr][tid] - mu2[nr]) * iv2[nr] * na_w[tid] + na_b[tid];
        xr[nr][tid] = gelu_f(v);
    }
    __syncthreads();
    // k projection
    {
        float ka[16];
        #pragma unroll
        for (int nr = 0; nr < 16; nr++) ka[nr] = 0.f;
        for (int c = 0; c < 128; c++){
            float wv = k_w[c*128 + tid];
            #pragma unroll
            for (int nr = 0; nr < 16; nr++) ka[nr] += xr[nr][c] * wv;
        }
        #pragma unroll
        for (int nr = 0; nr < 16; nr++) g_k[(b*16 + nr)*128 + tid] = ka[nr];
    }
    // v projection (256 out channels, 2 halves)
    for (int half = 0; half < 2; half++){
        int o3 = half*128 + tid;
        float va[16];
        #pragma unroll
        for (int nr = 0; nr < 16; nr++) va[nr] = 0.f;
        for (int c = 0; c < 128; c++){
            float wv = v_w[c*256 + o3];
            #pragma unroll
            for (int nr = 0; nr < 16; nr++) va[nr] += xr[nr][c] * wv;
        }
        #pragma unroll
        for (int nr = 0; nr < 16; nr++) vs[nr][o3] = va[nr];
    }
    __syncthreads();
    // CPE: dw 3x3 pad1 on 4x4 spatial, channel = cc
    for (int half = 0; half < 2; half++){
        int cc = half*128 + tid;
        float w9[9];
        #pragma unroll
        for (int j = 0; j < 9; j++) w9[j] = cpe_w[cc*9 + j];
        float cb = cpe_b[cc];
        #pragma unroll
        for (int nr = 0; nr < 16; nr++){
            int y = nr >> 2, x = nr & 3;
            float acc = cb;
            #pragma unroll
            for (int dy = -1; dy <= 1; dy++)
                #pragma unroll
                for (int dx = -1; dx <= 1; dx++){
                    int yy = y+dy, xx = x+dx;
                    if (yy >= 0 && yy < 4 && xx >= 0 && xx < 4)
                        acc += vs[yy*4+xx][cc] * w9[(dy+1)*3 + dx+1];
                }
            g_v[(b*16 + nr)*256 + cc] = vs[nr][cc] + acc;
        }
    }
}

// ---------------- K7: attention (fused, Nr=16) ----------------
__global__ void k_attn(){
    __shared__ float ks[8][16][16];
    __shared__ float vs2[16][256];
    int b  = blockIdx.x >> 7;          // 128 blocks per batch
    int tb = (blockIdx.x & 127) * 32;  // token base within batch
    for (int i = threadIdx.x; i < 2048; i += 256){
        int m = i >> 7, j = i & 127;
        ks[j>>4][m][j&15] = g_k[(b*16 + m)*128 + j];
    }
    for (int i = threadIdx.x; i < 4096; i += 256){
        int m = i >> 8, cc2 = i & 255;
        vs2[m][cc2] = g_v[(b*16 + m)*256 + cc2];
    }
    __syncthreads();
    int h = threadIdx.x >> 5;          // warp = one head
    int tk = threadIdx.x & 31;
    size_t n = (size_t)b*4096 + tb + tk;
    float qv[16];
    const float* qp = g_q + n*128 + h*16;
    #pragma unroll
    for (int d = 0; d < 16; d++) qv[d] = qp[d];
    float s[16];
    float mx = -1e30f;
    #pragma unroll
    for (int m = 0; m < 16; m++){
        float dot = 0.f;
        #pragma unroll
        for (int d = 0; d < 16; d++) dot += qv[d] * ks[h][m][d];
        s[m] = dot * 0.25f;
        mx = fmaxf(mx, s[m]);
    }
    float sum = 0.f;
    #pragma unroll
    for (int m = 0; m < 16; m++){ s[m] = expf(s[m] - mx); sum += s[m]; }
    float inv = 1.0f / sum;
    float* op = g_o + n*256 + h*32;
    #pragma unroll
    for (int d2 = 0; d2 < 32; d2++){
        float a = 0.f;
        #pragma unroll
        for (int m = 0; m < 16; m++) a += s[m] * vs2[m][h*32 + d2];
        op[d2] = a * inv;
    }
}

// ---------------- tiled SGEMM: C[M,N] = A[M,K] * W[K,N] (+bias,+resid,gelu,trans) ----------------
template<bool GELU, bool RESID, bool TRANSOUT>
__global__ __launch_bounds__(256) void k_gemm(
        const float* __restrict__ A, const float* __restrict__ Wt,
        const float* __restrict__ bias, const float* __restrict__ resid,
        float* __restrict__ Cc, int M, int Nn, int K){
    __shared__ float As[16][64];
    __shared__ float Bs[16][64];
    int tid = threadIdx.x;
    int m0 = blockIdx.y * 64, n0 = blockIdx.x * 64;
    int tx = tid & 15, ty = tid >> 4;
    int arow = tid >> 2, aq = tid & 3;
    int bk = tid >> 4, bq = tid & 15;
    float acc[4][4];
    #pragma unroll
    for (int i = 0; i < 4; i++)
        #pragma unroll
        for (int j = 0; j < 4; j++) acc[i][j] = 0.f;

    for (int k0 = 0; k0 < K; k0 += 16){
        float4 va = *(const float4*)(A + (size_t)(m0 + arow)*K + k0 + aq*4);
        As[aq*4+0][arow] = va.x;
        As[aq*4+1][arow] = va.y;
        As[aq*4+2][arow] = va.z;
        As[aq*4+3][arow] = va.w;
        *(float4*)&Bs[bk][bq*4] = *(const float4*)(Wt + (size_t)(k0 + bk)*Nn + n0 + bq*4);
        __syncthreads();
        #pragma unroll
        for (int kk = 0; kk < 16; kk++){
            float4 a4 = *(float4*)&As[kk][ty*4];
            float4 b4 = *(float4*)&Bs[kk][tx*4];
            acc[0][0] += a4.x*b4.x; acc[0][1] += a4.x*b4.y; acc[0][2] += a4.x*b4.z; acc[0][3] += a4.x*b4.w;
            acc[1][0] += a4.y*b4.x; acc[1][1] += a4.y*b4.y; acc[1][2] += a4.y*b4.z; acc[1][3] += a4.y*b4.w;
            acc[2][0] += a4.z*b4.x; acc[2][1] += a4.z*b4.y; acc[2][2] += a4.z*b4.z; acc[2][3] += a4.z*b4.w;
            acc[3][0] += a4.w*b4.x; acc[3][1] += a4.w*b4.y; acc[3][2] += a4.w*b4.z; acc[3][3] += a4.w*b4.w;
        }
        __syncthreads();
    }
    #pragma unroll
    for (int i = 0; i < 4; i++){
        int m = m0 + ty*4 + i;
        #pragma unroll
        for (int j = 0; j < 4; j++){
            int n = n0 + tx*4 + j;
            float v = acc[i][j];
            if (bias) v += bias[n];
            if (RESID) v += resid[(size_t)m*Nn + n];
            if (GELU) v = gelu_f(v);
            if (TRANSOUT){
                // out[b, n, tok] with Nn==256
                Cc[(((size_t)(m >> 12))*256 + n)*4096 + (m & 4095)] = v;
            } else {
                Cc[(size_t)m*Nn + n] = v;
            }
        }
    }
}

// ---------------- K: gnorm (LN over x2 half, 512) + write image layout ----------------
__global__ void k_gnorm(const float* __restrict__ gw, const float* __restrict__ gb){
    int token = blockIdx.x*8 + (threadIdx.x >> 5);
    int lane = threadIdx.x & 31;
    const float* p = g_h + (size_t)token*1024 + 512;
    float s = 0.f, q = 0.f;
    #pragma unroll
    for (int i = lane; i < 512; i += 32){ float v = p[i]; s += v; q += v*v; }
    #pragma unroll
    for (int off = 16; off > 0; off >>= 1){
        s += __shfl_xor_sync(0xffffffff, s, off);
        q += __shfl_xor_sync(0xffffffff, q, off);
    }
    float m = s * (1.0f/512.0f);
    float var = q * (1.0f/512.0f) - m*m;
    float iv = rsqrtf(var + 1e-5f);
    int b = token >> 12, n = token & 4095;
    #pragma unroll
    for (int i = lane; i < 512; i += 32)
        g_x2i[((size_t)(b*512 + i))*4096 + n] = (p[i] - m) * iv * gw[i] + gb[i];
}

// ---------------- K: depthwise 3x3 on 64x64, image layout ----------------
__global__ void k_gconv(const float* __restrict__ gw, const float* __restrict__ gb){
    int bc = blockIdx.x;               // b*512 + c
    int c = bc & 511;
    const float* src = g_x2i + (size_t)bc*4096;
    float* dst = g_x2c + (size_t)bc*4096;
    __shared__ float tl[66][66];
    for (int i = threadIdx.x; i < 66*66; i += 256){
        int y = i / 66 - 1, x = i % 66 - 1;
        tl[y+1][x+1] = (y >= 0 && y < 64 && x >= 0 && x < 64) ? src[y*64 + x] : 0.f;
    }
    __syncthreads();
    float w9[9];
    #pragma unroll
    for (int j = 0; j < 9; j++) w9[j] = gw[c*9 + j];
    float bias = gb[c];
    for (int i = threadIdx.x; i < 4096; i += 256){
        int y = i >> 6, x = i & 63;
        float a = bias;
        #pragma unroll
        for (int dy = 0; dy < 3; dy++)
            #pragma unroll
            for (int dx = 0; dx < 3; dx++)
                a += tl[y+dy][x+dx] * w9[dy*3 + dx];
        dst[i] = a;
    }
}

// ---------------- K: transpose x2c back to tokens and gate with x1 ----------------
__global__ void k_gatemlp(){
    int b = blockIdx.z;
    int c0 = blockIdx.y * 32, n0 = blockIdx.x * 32;
    int tx = threadIdx.x, ty = threadIdx.y;
    __shared__ float tl[32][33];
    for (int r = ty; r < 32; r += 8)
        tl[r][tx] = g_x2c[((size_t)(b*512 + c0 + r))*4096 + n0 + tx];
    __syncthreads();
    for (int r = ty; r < 32; r += 8){
        size_t tok = (size_t)b*4096 + n0 + r;
        g_gate[tok*512 + c0 + tx] = g_h[tok*1024 + c0 + tx] * tl[tx][r];
    }
}

// ---------------- launcher ----------------
extern "C" void kernel_launch(void* const* d_in, const int* in_sizes, int n_in,
                              void* d_out, int out_size){
    const float* x        = (const float*)d_in[0];
    const float* sda_w    = (const float*)d_in[1];
    const float* sda_gnw  = (const float*)d_in[2];
    const float* sda_gnb  = (const float*)d_in[3];
    const float* n1w      = (const float*)d_in[4];
    const float* n1b      = (const float*)d_in[5];
    const float* red_w    = (const float*)d_in[6];
    const float* red_b    = (const float*)d_in[7];
    const float* dw_w     = (const float*)d_in[8];
    const float* dw_b     = (const float*)d_in[9];
    const float* conv_w   = (const float*)d_in[10];
    const float* conv_b   = (const float*)d_in[11];
    const float* na_w     = (const float*)d_in[12];
    const float* na_b     = (const float*)d_in[13];
    const float* q_w      = (const float*)d_in[14];
    const float* k_w      = (const float*)d_in[15];
    const float* v_w      = (const float*)d_in[16];
    const float* cpe_w    = (const float*)d_in[17];
    const float* cpe_b    = (const float*)d_in[18];
    const float* proj_w   = (const float*)d_in[19];
    const float* proj_b   = (const float*)d_in[20];
    const float* n2w      = (const float*)d_in[21];
    const float* n2b      = (const float*)d_in[22];
    const float* fc1_w    = (const float*)d_in[23];
    const float* fc1_b    = (const float*)d_in[24];
    const float* gn_w     = (const float*)d_in[25];
    const float* gn_b     = (const float*)d_in[26];
    const float* gc_w     = (const float*)d_in[27];
    const float* gc_b     = (const float*)d_in[28];
    const float* fc2_w    = (const float*)d_in[29];
    const float* fc2_b    = (const float*)d_in[30];
    float* out = (float*)d_out;

    float *p_res, *p_tln, *p_q, *p_o, *p_gate;
    cudaGetSymbolAddress((void**)&p_res, g_res);
    cudaGetSymbolAddress((void**)&p_tln, g_tln);
    cudaGetSymbolAddress((void**)&p_q,   g_q);
    cudaGetSymbolAddress((void**)&p_o,   g_o);
    cudaGetSymbolAddress((void**)&p_gate,g_gate);
    float* p_h; cudaGetSymbolAddress((void**)&p_h, g_h);

    // 1. means
    k_mean<<<BB*CC, 256>>>(x);
    // 2. SDAM conv1d + GN + relu
    k_sdam<<<BB*16*2, 256>>>(sda_w, sda_gnw, sda_gnb);
    // 3. gate + to tokens
    k_gate<<<dim3(2, 8, BB*HH), dim3(32, 8)>>>(x);
    // 4. LN1
    k_ln256<<<BN/8, 256>>>(p_res, p_tln, n1w, n1b, 1e-6f);
    // 5. reduction conv chain
    k_red<<<BB*CC, 256>>>(red_w, red_b, dw_w, dw_b);
    // 6. small per-batch stage (1x1 + LN + gelu + k/v + CPE)
    k_small<<<BB, 128>>>(conv_w, conv_b, na_w, na_b, k_w, v_w, cpe_w, cpe_b);
    // 7. Q = tln @ q_w (no bias)
    k_gemm<false,false,false><<<dim3(CRD/64, BN/64), 256>>>(p_tln, q_w, nullptr, nullptr, p_q, BN, CRD, CC);
    // 8. attention
    k_attn<<<BN/32, 256>>>();
    // 9. proj + residual (in-place into g_res)
    k_gemm<false,true,false><<<dim3(CC/64, BN/64), 256>>>(p_o, proj_w, proj_b, p_res, p_res, BN, CC, CC);
    // 10. LN2
    k_ln256<<<BN/8, 256>>>(p_res, p_tln, n2w, n2b, 1e-6f);
    // 11. fc1 + gelu
    k_gemm<true,false,false><<<dim3(HID/64, BN/64), 256>>>(p_tln, fc1_w, fc1_b, nullptr, p_h, BN, HID, CC);
    // 12. gnorm of x2 half -> image layout
    k_gnorm<<<BN/8, 256>>>(gn_w, gn_b);
    // 13. depthwise 3x3
    k_gconv<<<BB*HALF, 256>>>(gc_w, gc_b);
    // 14. transpose back + gate with x1
    k_gatemlp<<<dim3(NN/32, HALF/32, BB), dim3(32, 8)>>>();
    // 15. fc2 + bias + residual, write transposed to [B,C,H,W]
    k_gemm<false,true,true><<<dim3(CC/64, BN/64), 256>>>(p_gate, fc2_w, fc2_b, p_res, out, BN, CC, HALF);
}

// round 8
// speedup vs baseline: 1.6710x; 1.6710x over previous
#include <cuda_runtime.h>
#include <cuda_bf16.h>
#include <math.h>
#include <stdint.h>

// ---------------- constants ----------------
#define BB 16
#define CC 256
#define HH 64
#define WW 64
#define NN 4096            // tokens per batch
#define BN (BB*NN)         // 65536 total tokens
#define CRD 128
#define NHD 8
#define NRD 16             // reduced tokens (4x4)
#define HID 1024
#define HALF 512

// ---------------- scratch (device globals; no allocation) ----------------
__device__ float g_xh[BB*CC*HH];          // row gates
__device__ float g_xw[BB*CC*WW];          // col gates
__device__ float g_res[(size_t)BN*CC];    // gated tokens -> later t2
__device__ float g_tln[(size_t)BN*CC];    // LN1 out -> later LN2 out
__device__ float g_q[(size_t)BN*CRD];
__device__ float g_o[(size_t)BN*CC];      // attention output tokens
__device__ float g_red[BB*CC*NRD];        // reduced+dw map tokens
__device__ float g_k[BB*NRD*CRD];
__device__ float g_v[BB*NRD*CC];
__device__ float g_h[(size_t)BN*HID];     // fc1 output (gelu'd)
__device__ float g_x2i[(size_t)BB*HALF*NN]; // gnormed x2, image layout
__device__ float g_x2c[(size_t)BB*HALF*NN]; // after gconv, image layout
__device__ float g_gate[(size_t)BN*HALF];   // x1*x2 token layout
// transposed weights [N,K]
__device__ float g_qT[CRD*CC];
__device__ float g_projT[CC*CC];
__device__ float g_fc1T[HID*CC];
__device__ float g_fc2T[CC*HALF];

__device__ __forceinline__ float gelu_f(float v){
    return 0.5f * v * (1.0f + erff(v * 0.70710678118654752f));
}

__device__ __forceinline__ uint32_t smem_u32(const void* p){
    uint32_t a;
    asm("{ .reg .u64 t; cvta.to.shared.u64 t, %1; cvt.u32.u64 %0, t; }" : "=r"(a) : "l"(p));
    return a;
}
__device__ __forceinline__ void cp16(uint32_t dst, const void* src){
    asm volatile("cp.async.cg.shared.global [%0], [%1], 16;" :: "r"(dst), "l"(src));
}
#define CP_COMMIT() asm volatile("cp.async.commit_group;" ::: "memory")
#define CP_WAIT0()  asm volatile("cp.async.wait_group 0;" ::: "memory")
#define CP_WAIT1()  asm volatile("cp.async.wait_group 1;" ::: "memory")

__device__ __forceinline__ void mma_tf32(float* c, const uint32_t* a, const uint32_t* b){
    asm volatile(
        "mma.sync.aligned.m16n8k8.row.col.f32.tf32.tf32.f32 "
        "{%0,%1,%2,%3}, {%4,%5,%6,%7}, {%8,%9}, {%0,%1,%2,%3};"
        : "+f"(c[0]), "+f"(c[1]), "+f"(c[2]), "+f"(c[3])
        : "r"(a[0]), "r"(a[1]), "r"(a[2]), "r"(a[3]), "r"(b[0]), "r"(b[1]));
}

// ---------------- weight transpose: WT[n*K+k] = W[k*N+n] ----------------
__global__ void k_tr(const float* __restrict__ W, float* __restrict__ WT, int K, int Nn){
    __shared__ float t[32][33];
    int k0 = blockIdx.y*32, n0 = blockIdx.x*32;
    int tx = threadIdx.x, ty = threadIdx.y;
    for (int r = ty; r < 32; r += 8)
        t[r][tx] = W[(size_t)(k0+r)*Nn + n0 + tx];
    __syncthreads();
    for (int r = ty; r < 32; r += 8)
        WT[(size_t)(n0+r)*K + k0 + tx] = t[tx][r];
}

// ---------------- mma.sync tf32 GEMM: C[M,N] = A[M,K] * WT[N,K]^T ----------------
// CTA 128x128, warp tile 64x32, K chunk 32, cp.async double buffer.
#define ROWF 36                     // padded row length in floats
#define BUFF (128*ROWF)             // one buffer, floats
#define GEMM_SMEM (4*BUFF*4)        // bytes: A0,A1,B0,B1

template<bool GELU, bool RESID, bool TRANSOUT>
__global__ __launch_bounds__(256, 2) void k_gemm_mma(
        const float* __restrict__ A, const float* __restrict__ WT,
        const float* __restrict__ bias, const float* __restrict__ resid,
        float* __restrict__ Cc, int M, int Nn, int K){
    extern __shared__ float sm[];
    float* Abuf[2] = { sm,          sm + BUFF };
    float* Bbuf[2] = { sm + 2*BUFF, sm + 3*BUFF };
    uint32_t sbase = smem_u32(sm);

    int tid = threadIdx.x, wid = tid >> 5, lane = tid & 31;
    int m0 = blockIdx.y * 128, n0 = blockIdx.x * 128;
    int wm = (wid & 1) * 64;        // warp m offset
    int wn = (wid >> 1) * 32;       // warp n offset

    float acc[4][4][4];
    #pragma unroll
    for (int i = 0; i < 4; i++)
        #pragma unroll
        for (int j = 0; j < 4; j++)
            #pragma unroll
            for (int q = 0; q < 4; q++) acc[i][j][q] = 0.f;

    int NC = K >> 5;
    // prefetch helper (inlined twice)
    int prow = tid >> 1;                 // 0..127
    int pseg0 = (tid & 1) * 4;           // segment base (of 8 16B segs per row)

    // prefetch chunk 0
    {
        const float* Ag = A  + (size_t)(m0 + prow)*K;
        const float* Bg = WT + (size_t)(n0 + prow)*K;
        uint32_t da = sbase + (0*BUFF + prow*ROWF)*4;
        uint32_t db = sbase + (2*BUFF + prow*ROWF)*4;
        #pragma unroll
        for (int s = 0; s < 4; s++){
            cp16(da + (pseg0+s)*16, Ag + (pseg0+s)*4);
            cp16(db + (pseg0+s)*16, Bg + (pseg0+s)*4);
        }
        CP_COMMIT();
    }

    for (int ch = 0; ch < NC; ch++){
        int buf = ch & 1;
        if (ch + 1 < NC){
            int nb = (ch + 1) & 1;
            const float* Ag = A  + (size_t)(m0 + prow)*K + (ch+1)*32;
            const float* Bg = WT + (size_t)(n0 + prow)*K + (ch+1)*32;
            uint32_t da = sbase + (nb*BUFF + prow*ROWF)*4;
            uint32_t db = sbase + ((2+nb)*BUFF + prow*ROWF)*4;
            #pragma unroll
            for (int s = 0; s < 4; s++){
                cp16(da + (pseg0+s)*16, Ag + (pseg0+s)*4);
                cp16(db + (pseg0+s)*16, Bg + (pseg0+s)*4);
            }
            CP_COMMIT();
            CP_WAIT1();
        } else {
            CP_WAIT0();
        }
        __syncthreads();

        const float* As = Abuf[buf];
        const float* Bs = Bbuf[buf];
        int c = lane & 3;
        int rbase = lane >> 2;          // 0..7
        #pragma unroll
        for (int kk = 0; kk < 4; kk++){
            int col = kk*8 + c;
            uint32_t af[4][4];
            #pragma unroll
            for (int mi = 0; mi < 4; mi++){
                int r = wm + mi*16 + rbase;
                af[mi][0] = __float_as_uint(As[r*ROWF + col]);
                af[mi][1] = __float_as_uint(As[(r+8)*ROWF + col]);
                af[mi][2] = __float_as_uint(As[r*ROWF + col + 4]);
                af[mi][3] = __float_as_uint(As[(r+8)*ROWF + col + 4]);
            }
            uint32_t bf[4][2];
            #pragma unroll
            for (int nj = 0; nj < 4; nj++){
                int rn = wn + nj*8 + rbase;
                bf[nj][0] = __float_as_uint(Bs[rn*ROWF + col]);
                bf[nj][1] = __float_as_uint(Bs[rn*ROWF + col + 4]);
            }
            #pragma unroll
            for (int mi = 0; mi < 4; mi++)
                #pragma unroll
                for (int nj = 0; nj < 4; nj++)
                    mma_tf32(acc[mi][nj], af[mi], bf[nj]);
        }
        __syncthreads();
    }

    // epilogue
    int rbase = lane >> 2;
    int cpair = (lane & 3) * 2;
    #pragma unroll
    for (int mi = 0; mi < 4; mi++){
        #pragma unroll
        for (int half = 0; half < 2; half++){
            int m = m0 + wm + mi*16 + rbase + half*8;
            #pragma unroll
            for (int nj = 0; nj < 4; nj++){
                int n = n0 + wn + nj*8 + cpair;
                float v0 = acc[mi][nj][half*2 + 0];
                float v1 = acc[mi][nj][half*2 + 1];
                if (bias){ v0 += bias[n]; v1 += bias[n+1]; }
                if (RESID){
                    const float* rp = resid + (size_t)m*Nn + n;
                    v0 += rp[0]; v1 += rp[1];
                }
                if (GELU){ v0 = gelu_f(v0); v1 = gelu_f(v1); }
                if (TRANSOUT){
                    size_t base = ((size_t)(m >> 12) * 256);
                    int mm = m & 4095;
                    Cc[(base + n + 0)*4096 + mm] = v0;
                    Cc[(base + n + 1)*4096 + mm] = v1;
                } else {
                    float2 vv = make_float2(v0, v1);
                    *(float2*)(Cc + (size_t)m*Nn + n) = vv;
                }
            }
        }
    }
}

// ---------------- K1: row/col means of x ----------------
__global__ void k_mean(const float* __restrict__ x){
    int bc = blockIdx.x;                      // b*256+c
    __shared__ float s[64][65];
    const float* p = x + (size_t)bc*4096;
    for (int i = threadIdx.x; i < 4096; i += 256) s[i>>6][i&63] = p[i];
    __syncthreads();
    int t = threadIdx.x;
    if (t < 64){
        float su = 0.f;
        #pragma unroll 8
        for (int w = 0; w < 64; w++) su += s[t][w];
        g_xh[bc*64 + t] = su * (1.0f/64.0f);
    } else if (t < 128){
        int w = t - 64;
        float su = 0.f;
        #pragma unroll 8
        for (int h = 0; h < 64; h++) su += s[h][w];
        g_xw[bc*64 + w] = su * (1.0f/64.0f);
    }
}

// ---------------- K2: dwconv1d(k=7,p=3) + GroupNorm(16) + ReLU ----------------
__global__ void k_sdam(const float* __restrict__ w7,
                       const float* __restrict__ gnw, const float* __restrict__ gnb){
    int id = blockIdx.x;            // b*32 + g*2 + which
    int which = id & 1;
    int g = (id >> 1) & 15;
    int b = id >> 5;
    float* src = which ? g_xw : g_xh;
    __shared__ float si[16][64];
    __shared__ float so[16][64];
    __shared__ float r1[256], r2[256];
    int base = (b*256 + g*16) * 64;
    for (int i = threadIdx.x; i < 1024; i += 256) si[i>>6][i&63] = src[base + i];
    __syncthreads();
    float p1 = 0.f, p2 = 0.f;
    for (int i = threadIdx.x; i < 1024; i += 256){
        int c = i >> 6, l = i & 63;
        const float* wk = w7 + (g*16 + c)*7;
        float acc = 0.f;
        #pragma unroll
        for (int k = 0; k < 7; k++){
            int ll = l - 3 + k;
            if (ll >= 0 && ll < 64) acc += si[c][ll] * wk[k];
        }
        so[c][l] = acc;
        p1 += acc; p2 += acc*acc;
    }
    r1[threadIdx.x] = p1; r2[threadIdx.x] = p2;
    __syncthreads();
    for (int st = 128; st > 0; st >>= 1){
        if (threadIdx.x < st){ r1[threadIdx.x] += r1[threadIdx.x+st]; r2[threadIdx.x] += r2[threadIdx.x+st]; }
        __syncthreads();
    }
    float mean = r1[0] * (1.0f/1024.0f);
    float var  = r2[0] * (1.0f/1024.0f) - mean*mean;
    float iv = rsqrtf(var + 1e-5f);
    for (int i = threadIdx.x; i < 1024; i += 256){
        int c = i >> 6, l = i & 63;
        float v = (so[c][l] - mean) * iv * gnw[g*16 + c] + gnb[g*16 + c];
        src[base + i] = fmaxf(v, 0.f);
    }
}

// ---------------- K3: gate x by xh*xw and transpose to tokens (g_res) ----------------
__global__ void k_gate(const float* __restrict__ x){
    int b = blockIdx.z >> 6, h = blockIdx.z & 63;
    int c0 = blockIdx.y * 32, w0 = blockIdx.x * 32;
    __shared__ float t2[32][33];
    int tx = threadIdx.x, ty = threadIdx.y;
    for (int r = ty; r < 32; r += 8){
        int c = c0 + r;
        int w = w0 + tx;
        t2[r][tx] = x[((size_t)(b*256 + c)*64 + h)*64 + w]
                  * g_xh[(b*256 + c)*64 + h] * g_xw[(b*256 + c)*64 + w];
    }
    __syncthreads();
    for (int r = ty; r < 32; r += 8){
        int w = w0 + r;
        g_res[((size_t)(b*4096) + h*64 + w)*256 + c0 + tx] = t2[tx][r];
    }
}

// ---------------- token LN over 256 (warp per token) ----------------
__global__ void k_ln256(const float* __restrict__ in, float* __restrict__ out,
                        const float* __restrict__ w, const float* __restrict__ bb, float eps){
    int token = blockIdx.x*8 + (threadIdx.x >> 5);
    int lane = threadIdx.x & 31;
    const float* p = in + (size_t)token*256;
    float s = 0.f, q = 0.f;
    #pragma unroll
    for (int i = lane; i < 256; i += 32){ float v = p[i]; s += v; q += v*v; }
    #pragma unroll
    for (int off = 16; off > 0; off >>= 1){
        s += __shfl_xor_sync(0xffffffff, s, off);
        q += __shfl_xor_sync(0xffffffff, q, off);
    }
    float m = s * (1.0f/256.0f);
    float var = q * (1.0f/256.0f) - m*m;
    float iv = rsqrtf(var + eps);
    #pragma unroll
    for (int i = lane; i < 256; i += 32)
        out[(size_t)token*256 + i] = (p[i] - m) * iv * w[i] + bb[i];
}

// ---------------- K5: reduction conv chain per (b,c): 64->16->4, then dw 3x3 ----------------
__global__ void k_red(const float* __restrict__ red_w, const float* __restrict__ red_b,
                      const float* __restrict__ dw_w, const float* __restrict__ dw_b){
    int bc = blockIdx.x;
    int b = bc >> 8, c = bc & 255;
    __shared__ float rw[16];
    __shared__ float dwv[9];
    __shared__ float o1[16][16];
    __shared__ float o2[4][4];
    int t = threadIdx.x;
    if (t < 16) rw[t] = red_w[c*16 + t];
    if (t >= 16 && t < 25) dwv[t-16] = dw_w[c*9 + (t-16)];
    __syncthreads();
    float rb = red_b[c];
    {   // stage 1: 16x16
        int u = t >> 4, v = t & 15;
        float acc = 0.f;
        #pragma unroll
        for (int p = 0; p < 4; p++)
            #pragma unroll
            for (int q = 0; q < 4; q++)
                acc += g_tln[((size_t)(b*4096) + (4*u+p)*64 + (4*v+q))*256 + c] * rw[p*4+q];
        o1[u][v] = acc + rb;
    }
    __syncthreads();
    if (t < 16){ // stage 2: 4x4
        int y = t >> 2, x = t & 3;
        float acc = 0.f;
        #pragma unroll
        for (int p = 0; p < 4; p++)
            #pragma unroll
            for (int q = 0; q < 4; q++)
                acc += o1[4*y+p][4*x+q] * rw[p*4+q];
        o2[y][x] = acc + rb;
    }
    __syncthreads();
    if (t < 16){ // dw 3x3 pad1
        int y = t >> 2, x = t & 3;
        float acc = dw_b[c];
        #pragma unroll
        for (int dy = -1; dy <= 1; dy++)
            #pragma unroll
            for (int dx = -1; dx <= 1; dx++){
                int yy = y+dy, xx = x+dx;
                if (yy >= 0 && yy < 4 && xx >= 0 && xx < 4)
                    acc += o2[yy][xx] * dwv[(dy+1)*3 + dx+1];
            }
        g_red[(b*256 + c)*16 + t] = acc;
    }
}

// ---------------- K6: per batch — 1x1 conv + LN + gelu, k/v proj, CPE ----------------
__global__ void k_small(const float* __restrict__ conv_w, const float* __restrict__ conv_b,
                        const float* __restrict__ na_w, const float* __restrict__ na_b,
                        const float* __restrict__ k_w, const float* __restrict__ v_w,
                        const float* __restrict__ cpe_w, const float* __restrict__ cpe_b){
    int b = blockIdx.x;
    int tid = threadIdx.x;   // 128 threads
    __shared__ float yr[256][16];
    __shared__ float xr[16][128];
    __shared__ float vs[16][256];
    __shared__ float mu2[16], iv2[16];
    for (int i = tid; i < 4096; i += 128) yr[i>>4][i&15] = g_red[b*4096 + i];
    __syncthreads();
    {
        float tmp[16];
        float cb = conv_b[tid];
        #pragma unroll
        for (int nr = 0; nr < 16; nr++) tmp[nr] = cb;
        for (int c = 0; c < 256; c++){
            float wv = conv_w[tid*256 + c];
            #pragma unroll
            for (int nr = 0; nr < 16; nr++) tmp[nr] += yr[c][nr] * wv;
        }
        #pragma unroll
        for (int nr = 0; nr < 16; nr++) xr[nr][tid] = tmp[nr];
    }
    __syncthreads();
    if (tid < 16){
        float s = 0.f, q = 0.f;
        for (int o = 0; o < 128; o++){ float v = xr[tid][o]; s += v; q += v*v; }
        float m = s * (1.0f/128.0f);
        float var = q * (1.0f/128.0f) - m*m;
        mu2[tid] = m; iv2[tid] = rsqrtf(var + 1e-5f);
    }
    __syncthreads();
    #pragma unroll
    for (int nr = 0; nr < 16; nr++){
        float v = (xr[nr][tid] - mu2[nr]) * iv2[nr] * na_w[tid] + na_b[tid];
        xr[nr][tid] = gelu_f(v);
    }
    __syncthreads();
    {
        float ka[16];
        #pragma unroll
        for (int nr = 0; nr < 16; nr++) ka[nr] = 0.f;
        for (int c = 0; c < 128; c++){
            float wv = k_w[c*128 + tid];
            #pragma unroll
            for (int nr = 0; nr < 16; nr++) ka[nr] += xr[nr][c] * wv;
        }
        #pragma unroll
        for (int nr = 0; nr < 16; nr++) g_k[(b*16 + nr)*128 + tid] = ka[nr];
    }
    for (int half = 0; half < 2; half++){
        int o3 = half*128 + tid;
        float va[16];
        #pragma unroll
        for (int nr = 0; nr < 16; nr++) va[nr] = 0.f;
        for (int c = 0; c < 128; c++){
            float wv = v_w[c*256 + o3];
            #pragma unroll
            for (int nr = 0; nr < 16; nr++) va[nr] += xr[nr][c] * wv;
        }
        #pragma unroll
        for (int nr = 0; nr < 16; nr++) vs[nr][o3] = va[nr];
    }
    __syncthreads();
    for (int half = 0; half < 2; half++){
        int cc = half*128 + tid;
        float w9[9];
        #pragma unroll
        for (int j = 0; j < 9; j++) w9[j] = cpe_w[cc*9 + j];
        float cb = cpe_b[cc];
        #pragma unroll
        for (int nr = 0; nr < 16; nr++){
            int y = nr >> 2, x = nr & 3;
            float acc = cb;
            #pragma unroll
            for (int dy = -1; dy <= 1; dy++)
                #pragma unroll
                for (int dx = -1; dx <= 1; dx++){
                    int yy = y+dy, xx = x+dx;
                    if (yy >= 0 && yy < 4 && xx >= 0 && xx < 4)
                        acc += vs[yy*4+xx][cc] * w9[(dy+1)*3 + dx+1];
                }
            g_v[(b*16 + nr)*256 + cc] = vs[nr][cc] + acc;
        }
    }
}

// ---------------- K7: attention (fused, Nr=16) ----------------
__global__ void k_attn(){
    __shared__ float ks[8][16][16];
    __shared__ float vs2[16][256];
    int b  = blockIdx.x >> 7;
    int tb = (blockIdx.x & 127) * 32;
    for (int i = threadIdx.x; i < 2048; i += 256){
        int m = i >> 7, j = i & 127;
        ks[j>>4][m][j&15] = g_k[(b*16 + m)*128 + j];
    }
    for (int i = threadIdx.x; i < 4096; i += 256){
        int m = i >> 8, cc2 = i & 255;
        vs2[m][cc2] = g_v[(b*16 + m)*256 + cc2];
    }
    __syncthreads();
    int h = threadIdx.x >> 5;
    int tk = threadIdx.x & 31;
    size_t n = (size_t)b*4096 + tb + tk;
    float qv[16];
    const float* qp = g_q + n*128 + h*16;
    #pragma unroll
    for (int d = 0; d < 16; d++) qv[d] = qp[d];
    float s[16];
    float mx = -1e30f;
    #pragma unroll
    for (int m = 0; m < 16; m++){
        float dot = 0.f;
        #pragma unroll
        for (int d = 0; d < 16; d++) dot += qv[d] * ks[h][m][d];
        s[m] = dot * 0.25f;
        mx = fmaxf(mx, s[m]);
    }
    float sum = 0.f;
    #pragma unroll
    for (int m = 0; m < 16; m++){ s[m] = expf(s[m] - mx); sum += s[m]; }
    float inv = 1.0f / sum;
    float* op = g_o + n*256 + h*32;
    #pragma unroll
    for (int d2 = 0; d2 < 32; d2++){
        float a = 0.f;
        #pragma unroll
        for (int m = 0; m < 16; m++) a += s[m] * vs2[m][h*32 + d2];
        op[d2] = a * inv;
    }
}

// ---------------- K: gnorm (LN over x2 half, 512) + write image layout ----------------
__global__ void k_gnorm(const float* __restrict__ gw, const float* __restrict__ gb){
    int token = blockIdx.x*8 + (threadIdx.x >> 5);
    int lane = threadIdx.x & 31;
    const float* p = g_h + (size_t)token*1024 + 512;
    float s = 0.f, q = 0.f;
    #pragma unroll
    for (int i = lane; i < 512; i += 32){ float v = p[i]; s += v; q += v*v; }
    #pragma unroll
    for (int off = 16; off > 0; off >>= 1){
        s += __shfl_xor_sync(0xffffffff, s, off);
        q += __shfl_xor_sync(0xffffffff, q, off);
    }
    float m = s * (1.0f/512.0f);
    float var = q * (1.0f/512.0f) - m*m;
    float iv = rsqrtf(var + 1e-5f);
    int b = token >> 12, n = token & 4095;
    #pragma unroll
    for (int i = lane; i < 512; i += 32)
        g_x2i[((size_t)(b*512 + i))*4096 + n] = (p[i] - m) * iv * gw[i] + gb[i];
}

// ---------------- K: depthwise 3x3 on 64x64, image layout ----------------
__global__ void k_gconv(const float* __restrict__ gw, const float* __restrict__ gb){
    int bc = blockIdx.x;
    int c = bc & 511;
    const float* src = g_x2i + (size_t)bc*4096;
    float* dst = g_x2c + (size_t)bc*4096;
    __shared__ float tl[66][66];
    for (int i = threadIdx.x; i < 66*66; i += 256){
        int y = i / 66 - 1, x = i % 66 - 1;
        tl[y+1][x+1] = (y >= 0 && y < 64 && x >= 0 && x < 64) ? src[y*64 + x] : 0.f;
    }
    __syncthreads();
    float w9[9];
    #pragma unroll
    for (int j = 0; j < 9; j++) w9[j] = gw[c*9 + j];
    float bias = gb[c];
    for (int i = threadIdx.x; i < 4096; i += 256){
        int y = i >> 6, x = i & 63;
        float a = bias;
        #pragma unroll
        for (int dy = 0; dy < 3; dy++)
            #pragma unroll
            for (int dx = 0; dx < 3; dx++)
                a += tl[y+dy][x+dx] * w9[dy*3 + dx];
        dst[i] = a;
    }
}

// ---------------- K: transpose x2c back to tokens and gate with x1 ----------------
__global__ void k_gatemlp(){
    int b = blockIdx.z;
    int c0 = blockIdx.y * 32, n0 = blockIdx.x * 32;
    int tx = threadIdx.x, ty = threadIdx.y;
    __shared__ float tl[32][33];
    for (int r = ty; r < 32; r += 8)
        tl[r][tx] = g_x2c[((size_t)(b*512 + c0 + r))*4096 + n0 + tx];
    __syncthreads();
    for (int r = ty; r < 32; r += 8){
        size_t tok = (size_t)b*4096 + n0 + r;
        g_gate[tok*512 + c0 + tx] = g_h[tok*1024 + c0 + tx] * tl[tx][r];
    }
}

// ---------------- launcher ----------------
extern "C" void kernel_launch(void* const* d_in, const int* in_sizes, int n_in,
                              void* d_out, int out_size){
    const float* x        = (const float*)d_in[0];
    const float* sda_w    = (const float*)d_in[1];
    const float* sda_gnw  = (const float*)d_in[2];
    const float* sda_gnb  = (const float*)d_in[3];
    const float* n1w      = (const float*)d_in[4];
    const float* n1b      = (const float*)d_in[5];
    const float* red_w    = (const float*)d_in[6];
    const float* red_b    = (const float*)d_in[7];
    const float* dw_w     = (const float*)d_in[8];
    const float* dw_b     = (const float*)d_in[9];
    const float* conv_w   = (const float*)d_in[10];
    const float* conv_b   = (const float*)d_in[11];
    const float* na_w     = (const float*)d_in[12];
    const float* na_b     = (const float*)d_in[13];
    const float* q_w      = (const float*)d_in[14];
    const float* k_w      = (const float*)d_in[15];
    const float* v_w      = (const float*)d_in[16];
    const float* cpe_w    = (const float*)d_in[17];
    const float* cpe_b    = (const float*)d_in[18];
    const float* proj_w   = (const float*)d_in[19];
    const float* proj_b   = (const float*)d_in[20];
    const float* n2w      = (const float*)d_in[21];
    const float* n2b      = (const float*)d_in[22];
    const float* fc1_w    = (const float*)d_in[23];
    const float* fc1_b    = (const float*)d_in[24];
    const float* gn_w     = (const float*)d_in[25];
    const float* gn_b     = (const float*)d_in[26];
    const float* gc_w     = (const float*)d_in[27];
    const float* gc_b     = (const float*)d_in[28];
    const float* fc2_w    = (const float*)d_in[29];
    const float* fc2_b    = (const float*)d_in[30];
    float* out = (float*)d_out;

    float *p_res, *p_tln, *p_q, *p_o, *p_gate, *p_h;
    float *p_qT, *p_projT, *p_fc1T, *p_fc2T;
    cudaGetSymbolAddress((void**)&p_res, g_res);
    cudaGetSymbolAddress((void**)&p_tln, g_tln);
    cudaGetSymbolAddress((void**)&p_q,   g_q);
    cudaGetSymbolAddress((void**)&p_o,   g_o);
    cudaGetSymbolAddress((void**)&p_gate,g_gate);
    cudaGetSymbolAddress((void**)&p_h,   g_h);
    cudaGetSymbolAddress((void**)&p_qT,  g_qT);
    cudaGetSymbolAddress((void**)&p_projT, g_projT);
    cudaGetSymbolAddress((void**)&p_fc1T, g_fc1T);
    cudaGetSymbolAddress((void**)&p_fc2T, g_fc2T);

    cudaFuncSetAttribute(k_gemm_mma<false,false,false>, cudaFuncAttributeMaxDynamicSharedMemorySize, GEMM_SMEM);
    cudaFuncSetAttribute(k_gemm_mma<false,true,false>,  cudaFuncAttributeMaxDynamicSharedMemorySize, GEMM_SMEM);
    cudaFuncSetAttribute(k_gemm_mma<true,false,false>,  cudaFuncAttributeMaxDynamicSharedMemorySize, GEMM_SMEM);
    cudaFuncSetAttribute(k_gemm_mma<false,true,true>,   cudaFuncAttributeMaxDynamicSharedMemorySize, GEMM_SMEM);

    // 0. weight transposes (tiny)
    k_tr<<<dim3(CRD/32, CC/32), dim3(32,8)>>>(q_w,    p_qT,   CC,   CRD);
    k_tr<<<dim3(CC/32,  CC/32), dim3(32,8)>>>(proj_w, p_projT, CC,  CC);
    k_tr<<<dim3(HID/32, CC/32), dim3(32,8)>>>(fc1_w,  p_fc1T, CC,   HID);
    k_tr<<<dim3(CC/32, HALF/32), dim3(32,8)>>>(fc2_w, p_fc2T, HALF, CC);

    // 1. means
    k_mean<<<BB*CC, 256>>>(x);
    // 2. SDAM conv1d + GN + relu
    k_sdam<<<BB*16*2, 256>>>(sda_w, sda_gnw, sda_gnb);
    // 3. gate + to tokens
    k_gate<<<dim3(2, 8, BB*HH), dim3(32, 8)>>>(x);
    // 4. LN1
    k_ln256<<<BN/8, 256>>>(p_res, p_tln, n1w, n1b, 1e-6f);
    // 5. reduction conv chain
    k_red<<<BB*CC, 256>>>(red_w, red_b, dw_w, dw_b);
    // 6. small per-batch stage (1x1 + LN + gelu + k/v + CPE)
    k_small<<<BB, 128>>>(conv_w, conv_b, na_w, na_b, k_w, v_w, cpe_w, cpe_b);
    // 7. Q = tln @ q_w (tensor core tf32, mma.sync)
    k_gemm_mma<false,false,false><<<dim3(CRD/128, BN/128), 256, GEMM_SMEM>>>(p_tln, p_qT, nullptr, nullptr, p_q, BN, CRD, CC);
    // 8. attention
    k_attn<<<BN/32, 256>>>();
    // 9. proj + residual (in-place into g_res)
    k_gemm_mma<false,true,false><<<dim3(CC/128, BN/128), 256, GEMM_SMEM>>>(p_o, p_projT, proj_b, p_res, p_res, BN, CC, CC);
    // 10. LN2
    k_ln256<<<BN/8, 256>>>(p_res, p_tln, n2w, n2b, 1e-6f);
    // 11. fc1 + gelu
    k_gemm_mma<true,false,false><<<dim3(HID/128, BN/128), 256, GEMM_SMEM>>>(p_tln, p_fc1T, fc1_b, nullptr, p_h, BN, HID, CC);
    // 12. gnorm of x2 half -> image layout
    k_gnorm<<<BN/8, 256>>>(gn_w, gn_b);
    // 13. depthwise 3x3
    k_gconv<<<BB*HALF, 256>>>(gc_w, gc_b);
    // 14. transpose back + gate with x1
    k_gatemlp<<<dim3(NN/32, HALF/32, BB), dim3(32, 8)>>>();
    // 15. fc2 + bias + residual, write transposed to [B,C,H,W]
    k_gemm_mma<false,true,true><<<dim3(CC/128, BN/128), 256, GEMM_SMEM>>>(p_gate, p_fc2T, fc2_b, p_res, out, BN, CC, HALF);
}